// round 2
// baseline (speedup 1.0000x reference)
#include <cuda_runtime.h>
#include <mma.h>

using namespace nvcuda;

#define NB     32
#define NC     512
#define NHEADS 8
#define ND     64
#define NSP    4096   // H*W

// Scratch (no allocations allowed): rounded W, folded per-batch W2
__device__ float g_Wr[NC * NC];
__device__ float g_W2[(size_t)NB * NC * NC];

__device__ __forceinline__ void st_tf32_4(float* p, float4 v) {
    p[0] = wmma::__float_to_tf32(v.x);
    p[1] = wmma::__float_to_tf32(v.y);
    p[2] = wmma::__float_to_tf32(v.z);
    p[3] = wmma::__float_to_tf32(v.w);
}

__global__ void round_w_kernel(const float* __restrict__ w) {
    int i = blockIdx.x * blockDim.x + threadIdx.x;
    if (i < NC * NC) g_Wr[i] = wmma::__float_to_tf32(w[i]);
}

// ---------------------------------------------------------------------------
// Kernel 1: per (b,h) block.
//   Phase A: stream L,G rows (64 x 4096) through SMEM in 64x32 chunks;
//            accumulate exact fp32 sum-of-squares per row during staging,
//            tf32 Gram S_raw[c][d] = L_c . G_d via WMMA.
//   Phase B: row-wise softmax of S_raw * invL[c]*invG[d]*temp  ->  A (in SMEM)
//   Phase C: W2 slice [512 x 64] = Wr[:, h*64:+64] @ A  (WMMA, K=64)
// ---------------------------------------------------------------------------
#define LDA1 36   // ld for 64x32 staging tiles (pad vs bank conflicts)
#define LDS1 68   // ld for 64x64 S / A tile

__global__ __launch_bounds__(256) void attn_kernel(
    const float* __restrict__ localf,
    const float* __restrict__ globalf,
    const float* __restrict__ temp)
{
    __shared__ float sLG[2 * 64 * LDA1];   // sL | sG ; aliased as sS after Gram
    __shared__ float sInv[128];            // invL[64] | invG[64]

    float* sL = sLG;
    float* sG = sLG + 64 * LDA1;
    float* sS = sLG;                        // 64*68 = 4352 <= 4608 floats

    const int h = blockIdx.x;
    const int b = blockIdx.y;
    const float* Lp = localf  + (size_t)(b * NC + h * ND) * NSP;
    const float* Gp = globalf + (size_t)(b * NC + h * ND) * NSP;

    const int t    = threadIdx.x;
    const int lane = t & 31;
    const int warp = t >> 5;
    const int srow = t >> 2;         // 0..63, fixed row per thread (for norms)
    const int scol = (t & 3) * 8;    // 0,8,16,24

    // Gram warp tiling: 8 warps cover 64x64; warp tile 32(m) x 16(n)
    const int m0 = (warp & 1) * 32;
    const int n0 = (warp >> 1) * 16;

    wmma::fragment<wmma::accumulator, 16, 16, 8, float> acc0, acc1;
    wmma::fill_fragment(acc0, 0.0f);
    wmma::fill_fragment(acc1, 0.0f);

    float sqL = 0.f, sqG = 0.f;

    for (int k0 = 0; k0 < NSP; k0 += 32) {
        const float* lrow = Lp + (size_t)srow * NSP + k0 + scol;
        const float* grow = Gp + (size_t)srow * NSP + k0 + scol;
        float4 l0 = ((const float4*)lrow)[0];
        float4 l1 = ((const float4*)lrow)[1];
        float4 g0 = ((const float4*)grow)[0];
        float4 g1 = ((const float4*)grow)[1];

        sqL += l0.x*l0.x + l0.y*l0.y + l0.z*l0.z + l0.w*l0.w
             + l1.x*l1.x + l1.y*l1.y + l1.z*l1.z + l1.w*l1.w;
        sqG += g0.x*g0.x + g0.y*g0.y + g0.z*g0.z + g0.w*g0.w
             + g1.x*g1.x + g1.y*g1.y + g1.z*g1.z + g1.w*g1.w;

        float* dl = sL + srow * LDA1 + scol;
        float* dg = sG + srow * LDA1 + scol;
        st_tf32_4(dl,     l0);
        st_tf32_4(dl + 4, l1);
        st_tf32_4(dg,     g0);
        st_tf32_4(dg + 4, g1);
        __syncthreads();

        #pragma unroll
        for (int kk = 0; kk < 32; kk += 8) {
            wmma::fragment<wmma::matrix_b, 16, 16, 8, wmma::precision::tf32, wmma::col_major> bf;
            wmma::load_matrix_sync(bf, sG + n0 * LDA1 + kk, LDA1);
            wmma::fragment<wmma::matrix_a, 16, 16, 8, wmma::precision::tf32, wmma::row_major> af;
            wmma::load_matrix_sync(af, sL + m0 * LDA1 + kk, LDA1);
            wmma::mma_sync(acc0, af, bf, acc0);
            wmma::load_matrix_sync(af, sL + (m0 + 16) * LDA1 + kk, LDA1);
            wmma::mma_sync(acc1, af, bf, acc1);
        }
        __syncthreads();
    }

    // Row norms: reduce over the 4 threads sharing each row (consecutive lanes)
    sqL += __shfl_xor_sync(0xffffffffu, sqL, 1);
    sqL += __shfl_xor_sync(0xffffffffu, sqL, 2);
    sqG += __shfl_xor_sync(0xffffffffu, sqG, 1);
    sqG += __shfl_xor_sync(0xffffffffu, sqG, 2);
    if ((t & 3) == 0) {
        sInv[srow]      = 1.f / fmaxf(sqrtf(sqL), 1e-12f);
        sInv[64 + srow] = 1.f / fmaxf(sqrtf(sqG), 1e-12f);
    }

    // Dump Gram accumulators to SMEM (aliases sL/sG; all reads completed)
    wmma::store_matrix_sync(sS + m0 * LDS1 + n0, acc0, LDS1, wmma::mem_row_major);
    wmma::store_matrix_sync(sS + (m0 + 16) * LDS1 + n0, acc1, LDS1, wmma::mem_row_major);
    __syncthreads();

    // Softmax over d (columns); one warp handles 8 rows
    const float tval = temp[h];
    for (int rr = warp * 8; rr < warp * 8 + 8; ++rr) {
        float il = sInv[rr] * tval;
        float x1 = sS[rr * LDS1 + lane]      * il * sInv[64 + lane];
        float x2 = sS[rr * LDS1 + 32 + lane] * il * sInv[96 + lane];
        float mx = fmaxf(x1, x2);
        #pragma unroll
        for (int o = 16; o > 0; o >>= 1)
            mx = fmaxf(mx, __shfl_xor_sync(0xffffffffu, mx, o));
        float e1 = expf(x1 - mx);
        float e2 = expf(x2 - mx);
        float s = e1 + e2;
        #pragma unroll
        for (int o = 16; o > 0; o >>= 1)
            s += __shfl_xor_sync(0xffffffffu, s, o);
        float is = 1.f / s;
        sS[rr * LDS1 + lane]      = wmma::__float_to_tf32(e1 * is);
        sS[rr * LDS1 + 32 + lane] = wmma::__float_to_tf32(e2 * is);
    }
    __syncthreads();

    // W2 slice: [512 x 64] = Wr[:, h*64:+64] @ A ; warp w -> rows w*64..+64
    const int o0 = warp * 64;
    wmma::fragment<wmma::accumulator, 16, 16, 8, float> wacc[4][4];
    #pragma unroll
    for (int i = 0; i < 4; ++i)
        #pragma unroll
        for (int j = 0; j < 4; ++j)
            wmma::fill_fragment(wacc[i][j], 0.0f);

    #pragma unroll
    for (int kk = 0; kk < 64; kk += 8) {
        wmma::fragment<wmma::matrix_b, 16, 16, 8, wmma::precision::tf32, wmma::row_major> bf[4];
        #pragma unroll
        for (int j = 0; j < 4; ++j)
            wmma::load_matrix_sync(bf[j], sS + kk * LDS1 + j * 16, LDS1);
        #pragma unroll
        for (int i = 0; i < 4; ++i) {
            wmma::fragment<wmma::matrix_a, 16, 16, 8, wmma::precision::tf32, wmma::row_major> af;
            wmma::load_matrix_sync(af, g_Wr + (size_t)(o0 + i * 16) * NC + h * ND + kk, NC);
            #pragma unroll
            for (int j = 0; j < 4; ++j)
                wmma::mma_sync(wacc[i][j], af, bf[j], wacc[i][j]);
        }
    }
    float* w2p = g_W2 + (size_t)b * NC * NC;
    #pragma unroll
    for (int i = 0; i < 4; ++i)
        #pragma unroll
        for (int j = 0; j < 4; ++j)
            wmma::store_matrix_sync(w2p + (size_t)(o0 + i * 16) * NC + h * ND + j * 16,
                                    wacc[i][j], NC, wmma::mem_row_major);
}

// ---------------------------------------------------------------------------
// Kernel 3: final[b] = W2[b] (512x512) @ G[b] (512x4096), tf32 WMMA.
// 128x128 block tile, KT=32, 8 warps (2x4), warp tile 64x32.
// ---------------------------------------------------------------------------
#define LDA3 36
#define LDB3 132

__global__ __launch_bounds__(256) void proj_kernel(
    const float* __restrict__ globalf, float* __restrict__ outp)
{
    __shared__ float sA[128 * LDA3];
    __shared__ float sB[32 * LDB3];

    const int b  = blockIdx.z;
    const int o0 = blockIdx.y * 128;
    const int n0 = blockIdx.x * 128;
    const float* Ap = g_W2 + (size_t)b * NC * NC;       // [512][512]
    const float* Bp = globalf + (size_t)b * NC * NSP;   // [512][4096]

    const int t    = threadIdx.x;
    const int warp = t >> 5;
    const int mw = (warp >> 2) * 64;
    const int nw = (warp & 3) * 32;

    const int arow = t >> 1, acol = (t & 1) * 16;
    const int brow = t >> 3, bcol = (t & 7) * 16;

    wmma::fragment<wmma::accumulator, 16, 16, 8, float> acc[4][2];
    #pragma unroll
    for (int i = 0; i < 4; ++i)
        #pragma unroll
        for (int j = 0; j < 2; ++j)
            wmma::fill_fragment(acc[i][j], 0.0f);

    for (int k0 = 0; k0 < NC; k0 += 32) {
        const float* ag = Ap + (size_t)(o0 + arow) * NC + k0 + acol;
        const float* bg = Bp + (size_t)(k0 + brow) * NSP + n0 + bcol;
        float4 av0 = ((const float4*)ag)[0];
        float4 av1 = ((const float4*)ag)[1];
        float4 av2 = ((const float4*)ag)[2];
        float4 av3 = ((const float4*)ag)[3];
        float4 bv0 = ((const float4*)bg)[0];
        float4 bv1 = ((const float4*)bg)[1];
        float4 bv2 = ((const float4*)bg)[2];
        float4 bv3 = ((const float4*)bg)[3];
        float* as = sA + arow * LDA3 + acol;
        float* bs = sB + brow * LDB3 + bcol;
        st_tf32_4(as,      av0);
        st_tf32_4(as + 4,  av1);
        st_tf32_4(as + 8,  av2);
        st_tf32_4(as + 12, av3);
        st_tf32_4(bs,      bv0);
        st_tf32_4(bs + 4,  bv1);
        st_tf32_4(bs + 8,  bv2);
        st_tf32_4(bs + 12, bv3);
        __syncthreads();

        #pragma unroll
        for (int kk = 0; kk < 32; kk += 8) {
            wmma::fragment<wmma::matrix_b, 16, 16, 8, wmma::precision::tf32, wmma::row_major> bf[2];
            #pragma unroll
            for (int j = 0; j < 2; ++j)
                wmma::load_matrix_sync(bf[j], sB + kk * LDB3 + nw + j * 16, LDB3);
            #pragma unroll
            for (int i = 0; i < 4; ++i) {
                wmma::fragment<wmma::matrix_a, 16, 16, 8, wmma::precision::tf32, wmma::row_major> af;
                wmma::load_matrix_sync(af, sA + (mw + i * 16) * LDA3 + kk, LDA3);
                #pragma unroll
                for (int j = 0; j < 2; ++j)
                    wmma::mma_sync(acc[i][j], af, bf[j], acc[i][j]);
            }
        }
        __syncthreads();
    }

    #pragma unroll
    for (int i = 0; i < 4; ++i)
        #pragma unroll
        for (int j = 0; j < 2; ++j)
            wmma::store_matrix_sync(
                outp + (size_t)(b * NC + o0 + mw + i * 16) * NSP + n0 + nw + j * 16,
                acc[i][j], NSP, wmma::mem_row_major);
}

extern "C" void kernel_launch(void* const* d_in, const int* in_sizes, int n_in,
                              void* d_out, int out_size) {
    (void)in_sizes; (void)n_in; (void)out_size;
    const float* localf  = (const float*)d_in[0];
    const float* globalf = (const float*)d_in[1];
    const float* temp    = (const float*)d_in[2];
    const float* projw   = (const float*)d_in[3];
    float* outp = (float*)d_out;

    round_w_kernel<<<(NC * NC + 511) / 512, 512>>>(projw);

    dim3 g1(NHEADS, NB);
    attn_kernel<<<g1, 256>>>(localf, globalf, temp);

    dim3 g3(NSP / 128, NC / 128, NB);
    proj_kernel<<<g3, 256>>>(globalf, outp);
}